// round 5
// baseline (speedup 1.0000x reference)
#include <cuda_runtime.h>

#define NB 8
#define ND 512
#define NN 1024
#define NH 8
#define KD 64

// Scratch (device globals; no runtime allocation allowed)
__device__ float g_q[NB * NN * ND];     // [b][n][h*64+k]
__device__ float g_k[NB * NN * KD];     // [b][m][k]
__device__ float g_v[NB * NN * KD];     // [b][m][v]
__device__ float g_o[NB * NN * ND];     // [b][n][h*64+v]
__device__ float g_wkv[128 * ND];       // packed [j][d]: j<64 -> key_proj, else value_proj

// ---------------------------------------------------------------------------
// Kernel 1: pack key_proj [D, 64] and value_proj [D, 64] into row-major [j][d]
// ---------------------------------------------------------------------------
__global__ void pack_wkv_kernel(const float* __restrict__ kp,
                                const float* __restrict__ vp) {
    int idx = blockIdx.x * 256 + threadIdx.x;   // 0 .. 128*512-1
    int j = idx >> 9;
    int d = idx & 511;
    g_wkv[idx] = (j < 64) ? kp[d * 64 + j] : vp[d * 64 + (j - 64)];
}

// ---------------------------------------------------------------------------
// Kernel 2: fused QKV projection.
// C[b][n][j] = sum_d x[b][d][n] * W[j][d],  j in [0, 640)
//   j <  512 : W = query_proj (already [j][d] row-major)
//   j >= 512 : W = g_wkv[j-512]
// Tile 64(n) x 64(j), K-chunk 32, 256 threads, 4x4 per thread.
// ---------------------------------------------------------------------------
__global__ void qkv_gemm_kernel(const float* __restrict__ x,
                                const float* __restrict__ wq) {
    int b  = blockIdx.z;
    int n0 = blockIdx.y * 64;
    int j0 = blockIdx.x * 64;
    const float* xb = x + (size_t)b * ND * NN;

    __shared__ float As[32][64];    // [dd][nn]
    __shared__ float Bs[32][65];    // [dd][jj] (+1 pad kills STS conflicts)

    int tid = threadIdx.x;
    int tx = tid & 15, ty = tid >> 4;
    float acc[4][4] = {};

    for (int d0 = 0; d0 < ND; d0 += 32) {
        // Load x tile: 32x64 floats, float4 along n (coalesced)
        #pragma unroll
        for (int r = 0; r < 2; r++) {
            int f4 = tid + 256 * r;              // 0..511
            int dd = f4 >> 4, c4 = (f4 & 15) << 2;
            *(float4*)&As[dd][c4] =
                *(const float4*)&xb[(size_t)(d0 + dd) * NN + n0 + c4];
        }
        // Load W tile: scalar, coalesced along d
        #pragma unroll
        for (int r = 0; r < 8; r++) {
            int lid = tid + 256 * r;             // 0..2047
            int dd = lid & 31, jj = lid >> 5;
            int j = j0 + jj;
            const float* wrow = (j < 512) ? (wq + (size_t)j * ND)
                                          : (g_wkv + (size_t)(j - 512) * ND);
            Bs[dd][jj] = wrow[d0 + dd];
        }
        __syncthreads();

        #pragma unroll
        for (int dd = 0; dd < 32; dd++) {
            float4 av = *(const float4*)&As[dd][ty << 2];
            float a0 = av.x, a1 = av.y, a2 = av.z, a3 = av.w;
            float bb[4];
            #pragma unroll
            for (int l = 0; l < 4; l++) bb[l] = Bs[dd][(tx << 2) + l];
            acc[0][0] += a0 * bb[0]; acc[0][1] += a0 * bb[1];
            acc[0][2] += a0 * bb[2]; acc[0][3] += a0 * bb[3];
            acc[1][0] += a1 * bb[0]; acc[1][1] += a1 * bb[1];
            acc[1][2] += a1 * bb[2]; acc[1][3] += a1 * bb[3];
            acc[2][0] += a2 * bb[0]; acc[2][1] += a2 * bb[1];
            acc[2][2] += a2 * bb[2]; acc[2][3] += a2 * bb[3];
            acc[3][0] += a3 * bb[0]; acc[3][1] += a3 * bb[1];
            acc[3][2] += a3 * bb[2]; acc[3][3] += a3 * bb[3];
        }
        __syncthreads();
    }

    // Write out: Q / K / V split by j (uniform per block since tiles are 64-wide)
    #pragma unroll
    for (int i = 0; i < 4; i++) {
        int n = n0 + (ty << 2) + i;
        #pragma unroll
        for (int l = 0; l < 4; l++) {
            int j = j0 + (tx << 2) + l;
            float val = acc[i][l];
            if (j < 512)      g_q[((size_t)(b * NN + n)) * ND + j] = val;
            else if (j < 576) g_k[((size_t)(b * NN + n)) * KD + (j - 512)] = val;
            else              g_v[((size_t)(b * NN + n)) * KD + (j - 576)] = val;
        }
    }
}

// ---------------------------------------------------------------------------
// Kernel 3: flash-style attention. One query row per thread, 128 threads/CTA.
// Grid: (8 q-blocks, 8 heads, 8 batch). K/V staged in smem 64 rows at a time;
// all smem compute reads are uniform across the warp (broadcast, conflict-free).
// ---------------------------------------------------------------------------
__global__ void __launch_bounds__(128, 1) attn_kernel() {
    int b = blockIdx.z, h = blockIdx.y;
    int n = blockIdx.x * 128 + threadIdx.x;

    __shared__ float Ks[64 * 64];
    __shared__ float Vs[64 * 64];

    float q[64];
    const float4* qp =
        (const float4*)(g_q + ((size_t)(b * NN + n)) * ND + h * KD);
    #pragma unroll
    for (int i = 0; i < 16; i++) {
        float4 t = qp[i];
        q[4*i+0] = t.x * 0.125f;   // fold softmax scale 1/sqrt(64)
        q[4*i+1] = t.y * 0.125f;
        q[4*i+2] = t.z * 0.125f;
        q[4*i+3] = t.w * 0.125f;
    }

    float o[64];
    #pragma unroll
    for (int v = 0; v < 64; v++) o[v] = 0.0f;
    float mrow = -1e30f, lsum = 0.0f;

    for (int mb = 0; mb < 16; mb++) {
        __syncthreads();
        const float4* kp = (const float4*)(g_k + (size_t)(b * NN + mb * 64) * KD);
        const float4* vp = (const float4*)(g_v + (size_t)(b * NN + mb * 64) * KD);
        #pragma unroll
        for (int r = 0; r < 8; r++) {
            int lid = threadIdx.x + 128 * r;     // 1024 float4 per tile
            ((float4*)Ks)[lid] = kp[lid];
            ((float4*)Vs)[lid] = vp[lid];
        }
        __syncthreads();

        #pragma unroll
        for (int c = 0; c < 2; c++) {
            float s[32];
            float bm = -1e30f;
            #pragma unroll
            for (int j = 0; j < 32; j++) {
                const float4* kr = (const float4*)(Ks + (c * 32 + j) * 64);
                float acc = 0.0f;
                #pragma unroll
                for (int d4 = 0; d4 < 16; d4++) {
                    float4 kv = kr[d4];
                    acc += q[4*d4+0] * kv.x + q[4*d4+1] * kv.y
                         + q[4*d4+2] * kv.z + q[4*d4+3] * kv.w;
                }
                s[j] = acc;
                bm = fmaxf(bm, acc);
            }
            if (bm > mrow) {
                float corr = __expf(mrow - bm);
                mrow = bm;
                lsum *= corr;
                #pragma unroll
                for (int v = 0; v < 64; v++) o[v] *= corr;
            }
            #pragma unroll
            for (int j = 0; j < 32; j++) {
                float p = __expf(s[j] - mrow);
                lsum += p;
                const float4* vr = (const float4*)(Vs + (c * 32 + j) * 64);
                #pragma unroll
                for (int v4 = 0; v4 < 16; v4++) {
                    float4 vv = vr[v4];
                    o[4*v4+0] += p * vv.x;
                    o[4*v4+1] += p * vv.y;
                    o[4*v4+2] += p * vv.z;
                    o[4*v4+3] += p * vv.w;
                }
            }
        }
    }

    float inv = 1.0f / lsum;
    float* op = g_o + ((size_t)(b * NN + n)) * ND + h * KD;
    #pragma unroll
    for (int v4 = 0; v4 < 16; v4++) {
        float4 t;
        t.x = o[4*v4+0] * inv; t.y = o[4*v4+1] * inv;
        t.z = o[4*v4+2] * inv; t.w = o[4*v4+3] * inv;
        ((float4*)op)[v4] = t;
    }
}

// ---------------------------------------------------------------------------
// Kernel 4: output projection.
// out[b][dout][n] = sum_j out_proj[dout][j] * g_o[b][n][j]   (j = h*64+v)
// Tile 64(dout) x 64(n), K-chunk 32 over j.
// ---------------------------------------------------------------------------
__global__ void out_gemm_kernel(const float* __restrict__ wout,
                                float* __restrict__ out) {
    int b   = blockIdx.z;
    int do0 = blockIdx.y * 64;
    int n0  = blockIdx.x * 64;

    __shared__ float Ws[64][36];   // [dout_local][jj] (pad 36, float4-aligned)
    __shared__ float Os[64][36];   // [n_local][jj]

    int tid = threadIdx.x;
    int tx = tid & 15, ty = tid >> 4;
    float acc[4][4] = {};

    const float* ob = g_o + (size_t)b * NN * ND;

    for (int j0 = 0; j0 < ND; j0 += 32) {
        #pragma unroll
        for (int r = 0; r < 2; r++) {
            int f4 = tid + 256 * r;              // 512 float4 per tile
            int row = f4 >> 3, c4 = (f4 & 7) << 2;
            *(float4*)&Ws[row][c4] =
                *(const float4*)&wout[(size_t)(do0 + row) * ND + j0 + c4];
            *(float4*)&Os[row][c4] =
                *(const float4*)&ob[(size_t)(n0 + row) * ND + j0 + c4];
        }
        __syncthreads();

        #pragma unroll
        for (int jj = 0; jj < 32; jj++) {
            float a[4], bb[4];
            #pragma unroll
            for (int i = 0; i < 4; i++) a[i] = Ws[(ty << 2) + i][jj];
            #pragma unroll
            for (int l = 0; l < 4; l++) bb[l] = Os[(tx << 2) + l][jj];
            #pragma unroll
            for (int i = 0; i < 4; i++)
                #pragma unroll
                for (int l = 0; l < 4; l++) acc[i][l] += a[i] * bb[l];
        }
        __syncthreads();
    }

    #pragma unroll
    for (int i = 0; i < 4; i++) {
        int dd = do0 + (ty << 2) + i;
        float4 t;
        t.x = acc[i][0]; t.y = acc[i][1]; t.z = acc[i][2]; t.w = acc[i][3];
        *(float4*)&out[((size_t)b * ND + dd) * NN + n0 + (tx << 2)] = t;
    }
}

// ---------------------------------------------------------------------------
// Launch
// ---------------------------------------------------------------------------
extern "C" void kernel_launch(void* const* d_in, const int* in_sizes, int n_in,
                              void* d_out, int out_size) {
    const float* x     = (const float*)d_in[0];  // [8, 512, 32, 32]
    const float* wq    = (const float*)d_in[1];  // [8, 64, 512]
    const float* wk    = (const float*)d_in[2];  // [512, 64]
    const float* wv    = (const float*)d_in[3];  // [512, 64]
    const float* wo    = (const float*)d_in[4];  // [512, 8, 64]
    float* out         = (float*)d_out;          // [8, 512, 32, 32]

    pack_wkv_kernel<<<256, 256>>>(wk, wv);
    qkv_gemm_kernel<<<dim3(10, 16, NB), 256>>>(x, wq);
    attn_kernel<<<dim3(8, NH, NB), 128>>>();
    out_gemm_kernel<<<dim3(16, 8, NB), 256>>>(wo, out);
}

// round 7
// speedup vs baseline: 4.2047x; 4.2047x over previous
#include <cuda_runtime.h>

#define NB 8
#define ND 512
#define NN 1024
#define NH 8
#define KD 64

__device__ float g_q[NB * NN * ND];
__device__ float g_k[NB * NN * KD];
__device__ float g_v[NB * NN * KD];
__device__ float g_o[NB * NN * ND];
__device__ float g_wkv[128 * ND];

__device__ __forceinline__ float2 tf32_split(float x) {
    unsigned h, l;
    asm("cvt.rna.tf32.f32 %0, %1;" : "=r"(h) : "f"(x));
    float r = x - __uint_as_float(h);
    asm("cvt.rna.tf32.f32 %0, %1;" : "=r"(l) : "f"(r));
    return make_float2(__uint_as_float(h), __uint_as_float(l));
}

__device__ __forceinline__ void mma_tf32(float* d, const unsigned* a,
                                         unsigned b0, unsigned b1) {
    asm("mma.sync.aligned.m16n8k8.row.col.f32.tf32.tf32.f32 "
        "{%0,%1,%2,%3}, {%4,%5,%6,%7}, {%8,%9}, {%0,%1,%2,%3};"
        : "+f"(d[0]), "+f"(d[1]), "+f"(d[2]), "+f"(d[3])
        : "r"(a[0]), "r"(a[1]), "r"(a[2]), "r"(a[3]), "r"(b0), "r"(b1));
}

// ---------------------------------------------------------------------------
// Kernel 1: pack wk/wv into row-major [j][d]
// ---------------------------------------------------------------------------
__global__ void pack_wkv_kernel(const float* __restrict__ kp,
                                const float* __restrict__ vp) {
    int idx = blockIdx.x * 256 + threadIdx.x;
    int j = idx >> 9, d = idx & 511;
    g_wkv[idx] = (j < 64) ? kp[d * 64 + j] : vp[d * 64 + (j - 64)];
}

// ---------------------------------------------------------------------------
// Kernel 2: QKV projection, fp32. Tile 128(n) x 64(j), K-chunk 16,
// 256 threads, 8x4 outputs/thread, float4 LDS on both operands.
// ---------------------------------------------------------------------------
__global__ void __launch_bounds__(256) qkv_gemm_kernel(const float* __restrict__ x,
                                                       const float* __restrict__ wq) {
    int b  = blockIdx.z;
    int n0 = blockIdx.y * 128;
    int j0 = blockIdx.x * 64;
    const float* xb = x + (size_t)b * ND * NN;

    __shared__ float As[16][128];
    __shared__ float Bs[16][68];

    int tid = threadIdx.x;
    int tx = tid & 15, ty = tid >> 4;
    float acc[8][4] = {};

    int jl = j0 + (tid >> 2);
    const float* wrow = (jl < 512) ? (wq + (size_t)jl * ND)
                                   : (g_wkv + (size_t)(jl - 512) * ND);
    int d4 = tid & 3;

    for (int d0 = 0; d0 < ND; d0 += 16) {
        #pragma unroll
        for (int r = 0; r < 2; r++) {
            int f4 = tid + 256 * r;
            int dd = f4 >> 5, c4 = f4 & 31;
            *(float4*)&As[dd][c4 * 4] =
                *(const float4*)&xb[(size_t)(d0 + dd) * NN + n0 + c4 * 4];
        }
        {
            float4 w4 = *(const float4*)&wrow[d0 + d4 * 4];
            int jc = tid >> 2;
            Bs[d4 * 4 + 0][jc] = w4.x;
            Bs[d4 * 4 + 1][jc] = w4.y;
            Bs[d4 * 4 + 2][jc] = w4.z;
            Bs[d4 * 4 + 3][jc] = w4.w;
        }
        __syncthreads();

        #pragma unroll
        for (int dd = 0; dd < 16; dd++) {
            float a[8], bb[4];
            *(float4*)&a[0] = *(const float4*)&As[dd][ty * 8];
            *(float4*)&a[4] = *(const float4*)&As[dd][ty * 8 + 4];
            *(float4*)&bb[0] = *(const float4*)&Bs[dd][tx * 4];
            #pragma unroll
            for (int i = 0; i < 8; i++)
                #pragma unroll
                for (int l = 0; l < 4; l++)
                    acc[i][l] += a[i] * bb[l];
        }
        __syncthreads();
    }

    int j = j0 + tx * 4;
    #pragma unroll
    for (int i = 0; i < 8; i++) {
        int n = n0 + ty * 8 + i;
        size_t bn = (size_t)(b * NN + n);
        float4 v = make_float4(acc[i][0], acc[i][1], acc[i][2], acc[i][3]);
        if (j < 512)       *(float4*)&g_q[bn * ND + j] = v;
        else if (j < 576)  *(float4*)&g_k[bn * KD + (j - 512)] = v;
        else               *(float4*)&g_v[bn * KD + (j - 576)] = v;
    }
}

// ---------------------------------------------------------------------------
// Kernel 3: flash attention, mma.sync tf32 3-term split (~fp32 accuracy).
// 64 queries/CTA, 4 warps (16 rows each). 32-key blocks in smem, pre-split.
// Grid: (16 q-tiles, 8 heads, 8 batch), 128 threads.
// ---------------------------------------------------------------------------
__global__ void __launch_bounds__(128) attn_mma_kernel() {
    int b = blockIdx.z, h = blockIdx.y;
    int n0 = blockIdx.x * 64;
    int tid = threadIdx.x;
    int warp = tid >> 5, lane = tid & 31;
    int g = lane >> 2, jj = lane & 3;
    int mw = warp * 16;

    __shared__ float Kh[32 * 68], Kl[32 * 68];
    __shared__ float Vh[32 * 68], Vl[32 * 68];

    // Q fragments with scale folded: 8 chunks of k8
    unsigned qh[8][4], ql[8][4];
    {
        const float* qbase = g_q + ((size_t)(b * NN) + n0 + mw) * ND + h * KD;
        #pragma unroll
        for (int kc = 0; kc < 8; kc++) {
            float xx[4];
            xx[0] = qbase[(size_t)g * ND + kc * 8 + jj];
            xx[1] = qbase[(size_t)(g + 8) * ND + kc * 8 + jj];
            xx[2] = qbase[(size_t)g * ND + kc * 8 + jj + 4];
            xx[3] = qbase[(size_t)(g + 8) * ND + kc * 8 + jj + 4];
            #pragma unroll
            for (int i = 0; i < 4; i++) {
                float2 sp = tf32_split(xx[i] * 0.125f);
                qh[kc][i] = __float_as_uint(sp.x);
                ql[kc][i] = __float_as_uint(sp.y);
            }
        }
    }

    float o[8][4];
    #pragma unroll
    for (int t = 0; t < 8; t++) { o[t][0] = o[t][1] = o[t][2] = o[t][3] = 0.f; }
    float m0 = -1e30f, m1 = -1e30f, l0 = 0.f, l1 = 0.f;

    for (int kb = 0; kb < 32; kb++) {
        __syncthreads();
        {
            const float4* kp = (const float4*)(g_k + ((size_t)b * NN + kb * 32) * KD);
            const float4* vp = (const float4*)(g_v + ((size_t)b * NN + kb * 32) * KD);
            #pragma unroll
            for (int r = 0; r < 4; r++) {
                int lid = tid + 128 * r;
                int key = lid >> 4, d4 = lid & 15;
                float4 kv = kp[key * 16 + d4];
                float2 s0 = tf32_split(kv.x), s1 = tf32_split(kv.y);
                float2 s2 = tf32_split(kv.z), s3 = tf32_split(kv.w);
                *(float4*)&Kh[key * 68 + d4 * 4] = make_float4(s0.x, s1.x, s2.x, s3.x);
                *(float4*)&Kl[key * 68 + d4 * 4] = make_float4(s0.y, s1.y, s2.y, s3.y);
                float4 vv = vp[key * 16 + d4];
                float2 t0 = tf32_split(vv.x), t1 = tf32_split(vv.y);
                float2 t2 = tf32_split(vv.z), t3 = tf32_split(vv.w);
                *(float4*)&Vh[key * 68 + d4 * 4] = make_float4(t0.x, t1.x, t2.x, t3.x);
                *(float4*)&Vl[key * 68 + d4 * 4] = make_float4(t0.y, t1.y, t2.y, t3.y);
            }
        }
        __syncthreads();

        // S = Q K^T  (m16 x n32 per warp)
        float s[4][4];
        #pragma unroll
        for (int nt = 0; nt < 4; nt++) s[nt][0] = s[nt][1] = s[nt][2] = s[nt][3] = 0.f;

        #pragma unroll
        for (int kc = 0; kc < 8; kc++) {
            unsigned bh0[4], bh1[4], bl0[4], bl1[4];
            #pragma unroll
            for (int nt = 0; nt < 4; nt++) {
                int idx = (nt * 8 + g) * 68 + kc * 8 + jj;
                bh0[nt] = __float_as_uint(Kh[idx]);
                bh1[nt] = __float_as_uint(Kh[idx + 4]);
                bl0[nt] = __float_as_uint(Kl[idx]);
                bl1[nt] = __float_as_uint(Kl[idx + 4]);
            }
            #pragma unroll
            for (int nt = 0; nt < 4; nt++) mma_tf32(s[nt], qh[kc], bh0[nt], bh1[nt]);
            #pragma unroll
            for (int nt = 0; nt < 4; nt++) mma_tf32(s[nt], qh[kc], bl0[nt], bl1[nt]);
            #pragma unroll
            for (int nt = 0; nt < 4; nt++) mma_tf32(s[nt], ql[kc], bh0[nt], bh1[nt]);
        }

        // online softmax for rows g and g+8
        float rm0 = -1e30f, rm1 = -1e30f;
        #pragma unroll
        for (int nt = 0; nt < 4; nt++) {
            rm0 = fmaxf(rm0, fmaxf(s[nt][0], s[nt][1]));
            rm1 = fmaxf(rm1, fmaxf(s[nt][2], s[nt][3]));
        }
        rm0 = fmaxf(rm0, __shfl_xor_sync(0xffffffffu, rm0, 1));
        rm0 = fmaxf(rm0, __shfl_xor_sync(0xffffffffu, rm0, 2));
        rm1 = fmaxf(rm1, __shfl_xor_sync(0xffffffffu, rm1, 1));
        rm1 = fmaxf(rm1, __shfl_xor_sync(0xffffffffu, rm1, 2));
        float mn0 = fmaxf(m0, rm0), mn1 = fmaxf(m1, rm1);
        float c0 = __expf(m0 - mn0), c1 = __expf(m1 - mn1);
        m0 = mn0; m1 = mn1;
        float sum0 = 0.f, sum1 = 0.f;
        #pragma unroll
        for (int nt = 0; nt < 4; nt++) {
            s[nt][0] = __expf(s[nt][0] - m0); sum0 += s[nt][0];
            s[nt][1] = __expf(s[nt][1] - m0); sum0 += s[nt][1];
            s[nt][2] = __expf(s[nt][2] - m1); sum1 += s[nt][2];
            s[nt][3] = __expf(s[nt][3] - m1); sum1 += s[nt][3];
        }
        l0 = l0 * c0 + sum0;
        l1 = l1 * c1 + sum1;
        #pragma unroll
        for (int t = 0; t < 8; t++) {
            o[t][0] *= c0; o[t][1] *= c0; o[t][2] *= c1; o[t][3] *= c1;
        }

        // O += P V ; P: C-frag -> A-frag via shfl
        #pragma unroll
        for (int kc = 0; kc < 4; kc++) {
            int s0l = (lane & 28) | (jj >> 1);
            int s1l = s0l + 2;
            float t00 = __shfl_sync(0xffffffffu, s[kc][0], s0l);
            float t01 = __shfl_sync(0xffffffffu, s[kc][1], s0l);
            float t20 = __shfl_sync(0xffffffffu, s[kc][2], s0l);
            float t21 = __shfl_sync(0xffffffffu, s[kc][3], s0l);
            float u00 = __shfl_sync(0xffffffffu, s[kc][0], s1l);
            float u01 = __shfl_sync(0xffffffffu, s[kc][1], s1l);
            float u20 = __shfl_sync(0xffffffffu, s[kc][2], s1l);
            float u21 = __shfl_sync(0xffffffffu, s[kc][3], s1l);
            bool od = (jj & 1) != 0;
            float af0 = od ? t01 : t00;
            float af1 = od ? t21 : t20;
            float af2 = od ? u01 : u00;
            float af3 = od ? u21 : u20;
            unsigned ah[4], al[4];
            float2 p;
            p = tf32_split(af0); ah[0] = __float_as_uint(p.x); al[0] = __float_as_uint(p.y);
            p = tf32_split(af1); ah[1] = __float_as_uint(p.x); al[1] = __float_as_uint(p.y);
            p = tf32_split(af2); ah[2] = __float_as_uint(p.x); al[2] = __float_as_uint(p.y);
            p = tf32_split(af3); ah[3] = __float_as_uint(p.x); al[3] = __float_as_uint(p.y);

            #pragma unroll
            for (int vt = 0; vt < 8; vt++) {
                int idx  = (kc * 8 + jj) * 68 + vt * 8 + g;
                int idx4 = idx + 4 * 68;
                unsigned b0h = __float_as_uint(Vh[idx]);
                unsigned b1h = __float_as_uint(Vh[idx4]);
                unsigned b0l = __float_as_uint(Vl[idx]);
                unsigned b1l = __float_as_uint(Vl[idx4]);
                mma_tf32(o[vt], ah, b0h, b1h);
                mma_tf32(o[vt], ah, b0l, b1l);
                mma_tf32(o[vt], al, b0h, b1h);
            }
        }
    }

    l0 += __shfl_xor_sync(0xffffffffu, l0, 1);
    l0 += __shfl_xor_sync(0xffffffffu, l0, 2);
    l1 += __shfl_xor_sync(0xffffffffu, l1, 1);
    l1 += __shfl_xor_sync(0xffffffffu, l1, 2);
    float inv0 = 1.0f / l0, inv1 = 1.0f / l1;

    float* ob = g_o + ((size_t)(b * NN) + n0 + mw) * ND + h * KD;
    #pragma unroll
    for (int vt = 0; vt < 8; vt++) {
        ob[(size_t)g * ND + vt * 8 + 2 * jj]           = o[vt][0] * inv0;
        ob[(size_t)g * ND + vt * 8 + 2 * jj + 1]       = o[vt][1] * inv0;
        ob[(size_t)(g + 8) * ND + vt * 8 + 2 * jj]     = o[vt][2] * inv1;
        ob[(size_t)(g + 8) * ND + vt * 8 + 2 * jj + 1] = o[vt][3] * inv1;
    }
}

// ---------------------------------------------------------------------------
// Kernel 4: output projection, fp32. Tile 64(dout) x 128(n), K-chunk 16,
// 256 threads, 4x8 outputs/thread, float4 LDS.
// out[b][dout][n] = sum_j wout[dout][j] * g_o[b][n][j]
// ---------------------------------------------------------------------------
__global__ void __launch_bounds__(256) out_gemm_kernel(const float* __restrict__ wout,
                                                       float* __restrict__ out) {
    int b   = blockIdx.z;
    int do0 = blockIdx.y * 64;
    int n0  = blockIdx.x * 128;

    __shared__ float Ws[16][68];    // [j][dout]
    __shared__ float Os[16][132];   // [j][n]

    int tid = threadIdx.x;
    int tx = tid & 15, ty = tid >> 4;
    float acc[4][8] = {};

    const float* ob = g_o + (size_t)b * NN * ND;
    int j4 = tid & 3;
    int rowW = tid >> 2;
    const float* wrow = wout + (size_t)(do0 + rowW) * ND;

    for (int j0 = 0; j0 < ND; j0 += 16) {
        {
            float4 w4 = *(const float4*)&wrow[j0 + j4 * 4];
            Ws[j4 * 4 + 0][rowW] = w4.x;
            Ws[j4 * 4 + 1][rowW] = w4.y;
            Ws[j4 * 4 + 2][rowW] = w4.z;
            Ws[j4 * 4 + 3][rowW] = w4.w;
        }
        #pragma unroll
        for (int r = 0; r < 2; r++) {
            int f4 = tid + 256 * r;
            int n = f4 >> 2, jq = f4 & 3;
            float4 o4 = *(const float4*)&ob[(size_t)(n0 + n) * ND + j0 + jq * 4];
            Os[jq * 4 + 0][n] = o4.x;
            Os[jq * 4 + 1][n] = o4.y;
            Os[jq * 4 + 2][n] = o4.z;
            Os[jq * 4 + 3][n] = o4.w;
        }
        __syncthreads();

        #pragma unroll
        for (int jd = 0; jd < 16; jd++) {
            float a[4], bb[8];
            *(float4*)&a[0]  = *(const float4*)&Ws[jd][ty * 4];
            *(float4*)&bb[0] = *(const float4*)&Os[jd][tx * 4];
            *(float4*)&bb[4] = *(const float4*)&Os[jd][64 + tx * 4];
            #pragma unroll
            for (int i = 0; i < 4; i++)
                #pragma unroll
                for (int l = 0; l < 8; l++)
                    acc[i][l] += a[i] * bb[l];
        }
        __syncthreads();
    }

    #pragma unroll
    for (int i = 0; i < 4; i++) {
        int dd = do0 + ty * 4 + i;
        float4 v0 = make_float4(acc[i][0], acc[i][1], acc[i][2], acc[i][3]);
        float4 v1 = make_float4(acc[i][4], acc[i][5], acc[i][6], acc[i][7]);
        *(float4*)&out[((size_t)b * ND + dd) * NN + n0 + tx * 4]      = v0;
        *(float4*)&out[((size_t)b * ND + dd) * NN + n0 + 64 + tx * 4] = v1;
    }
}

// ---------------------------------------------------------------------------
// Launch
// ---------------------------------------------------------------------------
extern "C" void kernel_launch(void* const* d_in, const int* in_sizes, int n_in,
                              void* d_out, int out_size) {
    const float* x  = (const float*)d_in[0];  // [8, 512, 32, 32]
    const float* wq = (const float*)d_in[1];  // [8, 64, 512]
    const float* wk = (const float*)d_in[2];  // [512, 64]
    const float* wv = (const float*)d_in[3];  // [512, 64]
    const float* wo = (const float*)d_in[4];  // [512, 8, 64]
    float* out      = (float*)d_out;          // [8, 512, 32, 32]

    pack_wkv_kernel<<<256, 256>>>(wk, wv);
    qkv_gemm_kernel<<<dim3(10, 8, NB), 256>>>(x, wq);
    attn_mma_kernel<<<dim3(16, NH, NB), 128>>>();
    out_gemm_kernel<<<dim3(8, 8, NB), 256>>>(wo, out);
}

// round 8
// speedup vs baseline: 4.5130x; 1.0733x over previous
#include <cuda_runtime.h>

#define NB 8
#define ND 512
#define NN 1024
#define NH 8
#define KD 64

__device__ float g_q[NB * NN * ND];
__device__ float g_k[NB * NN * KD];
__device__ float g_v[NB * NN * KD];
__device__ float g_o[NB * NN * ND];
__device__ float g_wkv[128 * ND];

__device__ __forceinline__ float2 tf32_split(float x) {
    unsigned h, l;
    asm("cvt.rna.tf32.f32 %0, %1;" : "=r"(h) : "f"(x));
    float r = x - __uint_as_float(h);
    asm("cvt.rna.tf32.f32 %0, %1;" : "=r"(l) : "f"(r));
    return make_float2(__uint_as_float(h), __uint_as_float(l));
}

__device__ __forceinline__ void mma_tf32(float* d, const unsigned* a,
                                         unsigned b0, unsigned b1) {
    asm("mma.sync.aligned.m16n8k8.row.col.f32.tf32.tf32.f32 "
        "{%0,%1,%2,%3}, {%4,%5,%6,%7}, {%8,%9}, {%0,%1,%2,%3};"
        : "+f"(d[0]), "+f"(d[1]), "+f"(d[2]), "+f"(d[3])
        : "r"(a[0]), "r"(a[1]), "r"(a[2]), "r"(a[3]), "r"(b0), "r"(b1));
}

// ---------------------------------------------------------------------------
// Kernel 1: pack wk/wv into row-major [j][d]
// ---------------------------------------------------------------------------
__global__ void pack_wkv_kernel(const float* __restrict__ kp,
                                const float* __restrict__ vp) {
    int idx = blockIdx.x * 256 + threadIdx.x;
    int j = idx >> 9, d = idx & 511;
    g_wkv[idx] = (j < 64) ? kp[d * 64 + j] : vp[d * 64 + (j - 64)];
}

// ---------------------------------------------------------------------------
// Kernel 2: QKV projection via split-tf32 mma.sync.
// C[b][n][j] = sum_d x[b][d][n] * W[j][d]
// A = rx[n][d] (row-major), B = W[j][d] (col-major n=j, k=d).
// CTA tile: 128(n) x 64(j), K-chunk 16. 256 threads = 8 warps, warp w owns
// rows w*16..w*16+15 and all 64 j columns (8 n8-tiles).
// smem layouts [row][k] with pad 20 -> conflict-free fragment LDS.
// ---------------------------------------------------------------------------
__global__ void __launch_bounds__(256) qkv_mma_kernel(const float* __restrict__ x,
                                                      const float* __restrict__ wq) {
    int b  = blockIdx.z;
    int n0 = blockIdx.y * 128;
    int jblk = blockIdx.x;          // 0..7 Q, 8 K, 9 V
    int j0 = jblk * 64;
    const float* xb = x + (size_t)b * ND * NN;

    __shared__ float Ah[128][20], Al[128][20];   // [n][d16]
    __shared__ float Bh[64][20],  Bl[64][20];    // [j][d16]

    int tid = threadIdx.x;
    int warp = tid >> 5, lane = tid & 31;
    int g = lane >> 2, jj = lane & 3;
    int mw = warp * 16;

    float acc[8][4] = {};

    // B loader: thread -> (j row, d quad)
    int brow = tid >> 2, bd4 = tid & 3;
    int jglob = j0 + brow;
    const float* wrow = (jglob < 512) ? (wq + (size_t)jglob * ND)
                                      : (g_wkv + (size_t)(jglob - 512) * ND);
    // A loader: thread -> n = tid&127, d-group (tid>>7)*8
    int an = tid & 127;
    int adg = (tid >> 7) * 8;

    for (int d0 = 0; d0 < ND; d0 += 16) {
        {   // stage B (direct row copy, split at store)
            float4 w4 = *(const float4*)&wrow[d0 + bd4 * 4];
            float2 s0 = tf32_split(w4.x), s1 = tf32_split(w4.y);
            float2 s2 = tf32_split(w4.z), s3 = tf32_split(w4.w);
            *(float4*)&Bh[brow][bd4 * 4] = make_float4(s0.x, s1.x, s2.x, s3.x);
            *(float4*)&Bl[brow][bd4 * 4] = make_float4(s0.y, s1.y, s2.y, s3.y);
        }
        {   // stage A: gather 8 d-values for fixed n (coalesced scalar LDG)
            float xv[8];
            #pragma unroll
            for (int i = 0; i < 8; i++)
                xv[i] = xb[(size_t)(d0 + adg + i) * NN + n0 + an];
            float2 p0 = tf32_split(xv[0]), p1 = tf32_split(xv[1]);
            float2 p2 = tf32_split(xv[2]), p3 = tf32_split(xv[3]);
            *(float4*)&Ah[an][adg]     = make_float4(p0.x, p1.x, p2.x, p3.x);
            *(float4*)&Al[an][adg]     = make_float4(p0.y, p1.y, p2.y, p3.y);
            float2 p4 = tf32_split(xv[4]), p5 = tf32_split(xv[5]);
            float2 p6 = tf32_split(xv[6]), p7 = tf32_split(xv[7]);
            *(float4*)&Ah[an][adg + 4] = make_float4(p4.x, p5.x, p6.x, p7.x);
            *(float4*)&Al[an][adg + 4] = make_float4(p4.y, p5.y, p6.y, p7.y);
        }
        __syncthreads();

        #pragma unroll
        for (int kc = 0; kc < 2; kc++) {
            int k0 = kc * 8;
            unsigned ah[4], al[4];
            ah[0] = __float_as_uint(Ah[mw + g][k0 + jj]);
            ah[1] = __float_as_uint(Ah[mw + g + 8][k0 + jj]);
            ah[2] = __float_as_uint(Ah[mw + g][k0 + jj + 4]);
            ah[3] = __float_as_uint(Ah[mw + g + 8][k0 + jj + 4]);
            al[0] = __float_as_uint(Al[mw + g][k0 + jj]);
            al[1] = __float_as_uint(Al[mw + g + 8][k0 + jj]);
            al[2] = __float_as_uint(Al[mw + g][k0 + jj + 4]);
            al[3] = __float_as_uint(Al[mw + g + 8][k0 + jj + 4]);
            #pragma unroll
            for (int jt = 0; jt < 8; jt++) {
                unsigned bh0 = __float_as_uint(Bh[jt * 8 + g][k0 + jj]);
                unsigned bh1 = __float_as_uint(Bh[jt * 8 + g][k0 + jj + 4]);
                unsigned bl0 = __float_as_uint(Bl[jt * 8 + g][k0 + jj]);
                unsigned bl1 = __float_as_uint(Bl[jt * 8 + g][k0 + jj + 4]);
                mma_tf32(acc[jt], ah, bh0, bh1);
                mma_tf32(acc[jt], ah, bl0, bl1);
                mma_tf32(acc[jt], al, bh0, bh1);
            }
        }
        __syncthreads();
    }

    // Epilogue: c0=C[g][2jj], c1=C[g][2jj+1], c2=C[g+8][2jj], c3=C[g+8][2jj+1]
    int n = n0 + mw + g;
    size_t bn0 = (size_t)(b * NN + n);
    size_t bn1 = (size_t)(b * NN + n + 8);
    #pragma unroll
    for (int jt = 0; jt < 8; jt++) {
        int jloc = jt * 8 + 2 * jj;
        float2 v0 = make_float2(acc[jt][0], acc[jt][1]);
        float2 v1 = make_float2(acc[jt][2], acc[jt][3]);
        if (jblk < 8) {
            *(float2*)&g_q[bn0 * ND + j0 + jloc] = v0;
            *(float2*)&g_q[bn1 * ND + j0 + jloc] = v1;
        } else if (jblk == 8) {
            *(float2*)&g_k[bn0 * KD + jloc] = v0;
            *(float2*)&g_k[bn1 * KD + jloc] = v1;
        } else {
            *(float2*)&g_v[bn0 * KD + jloc] = v0;
            *(float2*)&g_v[bn1 * KD + jloc] = v1;
        }
    }
}

// ---------------------------------------------------------------------------
// Kernel 3: flash attention, mma.sync tf32 3-term split (unchanged logic;
// V smem pad 68 -> 72 to kill 2-way LDS conflict in the PV loop).
// ---------------------------------------------------------------------------
__global__ void __launch_bounds__(128) attn_mma_kernel() {
    int b = blockIdx.z, h = blockIdx.y;
    int n0 = blockIdx.x * 64;
    int tid = threadIdx.x;
    int warp = tid >> 5, lane = tid & 31;
    int g = lane >> 2, jj = lane & 3;
    int mw = warp * 16;

    __shared__ float Kh[32 * 68], Kl[32 * 68];
    __shared__ float Vh[32 * 72], Vl[32 * 72];

    unsigned qh[8][4], ql[8][4];
    {
        const float* qbase = g_q + ((size_t)(b * NN) + n0 + mw) * ND + h * KD;
        #pragma unroll
        for (int kc = 0; kc < 8; kc++) {
            float xx[4];
            xx[0] = qbase[(size_t)g * ND + kc * 8 + jj];
            xx[1] = qbase[(size_t)(g + 8) * ND + kc * 8 + jj];
            xx[2] = qbase[(size_t)g * ND + kc * 8 + jj + 4];
            xx[3] = qbase[(size_t)(g + 8) * ND + kc * 8 + jj + 4];
            #pragma unroll
            for (int i = 0; i < 4; i++) {
                float2 sp = tf32_split(xx[i] * 0.125f);
                qh[kc][i] = __float_as_uint(sp.x);
                ql[kc][i] = __float_as_uint(sp.y);
            }
        }
    }

    float o[8][4];
    #pragma unroll
    for (int t = 0; t < 8; t++) { o[t][0] = o[t][1] = o[t][2] = o[t][3] = 0.f; }
    float m0 = -1e30f, m1 = -1e30f, l0 = 0.f, l1 = 0.f;

    for (int kb = 0; kb < 32; kb++) {
        __syncthreads();
        {
            const float4* kp = (const float4*)(g_k + ((size_t)b * NN + kb * 32) * KD);
            const float4* vp = (const float4*)(g_v + ((size_t)b * NN + kb * 32) * KD);
            #pragma unroll
            for (int r = 0; r < 4; r++) {
                int lid = tid + 128 * r;
                int key = lid >> 4, d4 = lid & 15;
                float4 kv = kp[key * 16 + d4];
                float2 s0 = tf32_split(kv.x), s1 = tf32_split(kv.y);
                float2 s2 = tf32_split(kv.z), s3 = tf32_split(kv.w);
                *(float4*)&Kh[key * 68 + d4 * 4] = make_float4(s0.x, s1.x, s2.x, s3.x);
                *(float4*)&Kl[key * 68 + d4 * 4] = make_float4(s0.y, s1.y, s2.y, s3.y);
                float4 vv = vp[key * 16 + d4];
                float2 t0 = tf32_split(vv.x), t1 = tf32_split(vv.y);
                float2 t2 = tf32_split(vv.z), t3 = tf32_split(vv.w);
                *(float4*)&Vh[key * 72 + d4 * 4] = make_float4(t0.x, t1.x, t2.x, t3.x);
                *(float4*)&Vl[key * 72 + d4 * 4] = make_float4(t0.y, t1.y, t2.y, t3.y);
            }
        }
        __syncthreads();

        float s[4][4];
        #pragma unroll
        for (int nt = 0; nt < 4; nt++) s[nt][0] = s[nt][1] = s[nt][2] = s[nt][3] = 0.f;

        #pragma unroll
        for (int kc = 0; kc < 8; kc++) {
            unsigned bh0[4], bh1[4], bl0[4], bl1[4];
            #pragma unroll
            for (int nt = 0; nt < 4; nt++) {
                int idx = (nt * 8 + g) * 68 + kc * 8 + jj;
                bh0[nt] = __float_as_uint(Kh[idx]);
                bh1[nt] = __float_as_uint(Kh[idx + 4]);
                bl0[nt] = __float_as_uint(Kl[idx]);
                bl1[nt] = __float_as_uint(Kl[idx + 4]);
            }
            #pragma unroll
            for (int nt = 0; nt < 4; nt++) mma_tf32(s[nt], qh[kc], bh0[nt], bh1[nt]);
            #pragma unroll
            for (int nt = 0; nt < 4; nt++) mma_tf32(s[nt], qh[kc], bl0[nt], bl1[nt]);
            #pragma unroll
            for (int nt = 0; nt < 4; nt++) mma_tf32(s[nt], ql[kc], bh0[nt], bh1[nt]);
        }

        float rm0 = -1e30f, rm1 = -1e30f;
        #pragma unroll
        for (int nt = 0; nt < 4; nt++) {
            rm0 = fmaxf(rm0, fmaxf(s[nt][0], s[nt][1]));
            rm1 = fmaxf(rm1, fmaxf(s[nt][2], s[nt][3]));
        }
        rm0 = fmaxf(rm0, __shfl_xor_sync(0xffffffffu, rm0, 1));
        rm0 = fmaxf(rm0, __shfl_xor_sync(0xffffffffu, rm0, 2));
        rm1 = fmaxf(rm1, __shfl_xor_sync(0xffffffffu, rm1, 1));
        rm1 = fmaxf(rm1, __shfl_xor_sync(0xffffffffu, rm1, 2));
        float mn0 = fmaxf(m0, rm0), mn1 = fmaxf(m1, rm1);
        float c0 = __expf(m0 - mn0), c1 = __expf(m1 - mn1);
        m0 = mn0; m1 = mn1;
        float sum0 = 0.f, sum1 = 0.f;
        #pragma unroll
        for (int nt = 0; nt < 4; nt++) {
            s[nt][0] = __expf(s[nt][0] - m0); sum0 += s[nt][0];
            s[nt][1] = __expf(s[nt][1] - m0); sum0 += s[nt][1];
            s[nt][2] = __expf(s[nt][2] - m1); sum1 += s[nt][2];
            s[nt][3] = __expf(s[nt][3] - m1); sum1 += s[nt][3];
        }
        l0 = l0 * c0 + sum0;
        l1 = l1 * c1 + sum1;
        #pragma unroll
        for (int t = 0; t < 8; t++) {
            o[t][0] *= c0; o[t][1] *= c0; o[t][2] *= c1; o[t][3] *= c1;
        }

        #pragma unroll
        for (int kc = 0; kc < 4; kc++) {
            int s0l = (lane & 28) | (jj >> 1);
            int s1l = s0l + 2;
            float t00 = __shfl_sync(0xffffffffu, s[kc][0], s0l);
            float t01 = __shfl_sync(0xffffffffu, s[kc][1], s0l);
            float t20 = __shfl_sync(0xffffffffu, s[kc][2], s0l);
            float t21 = __shfl_sync(0xffffffffu, s[kc][3], s0l);
            float u00 = __shfl_sync(0xffffffffu, s[kc][0], s1l);
            float u01 = __shfl_sync(0xffffffffu, s[kc][1], s1l);
            float u20 = __shfl_sync(0xffffffffu, s[kc][2], s1l);
            float u21 = __shfl_sync(0xffffffffu, s[kc][3], s1l);
            bool od = (jj & 1) != 0;
            float af0 = od ? t01 : t00;
            float af1 = od ? t21 : t20;
            float af2 = od ? u01 : u00;
            float af3 = od ? u21 : u20;
            unsigned ah[4], al[4];
            float2 p;
            p = tf32_split(af0); ah[0] = __float_as_uint(p.x); al[0] = __float_as_uint(p.y);
            p = tf32_split(af1); ah[1] = __float_as_uint(p.x); al[1] = __float_as_uint(p.y);
            p = tf32_split(af2); ah[2] = __float_as_uint(p.x); al[2] = __float_as_uint(p.y);
            p = tf32_split(af3); ah[3] = __float_as_uint(p.x); al[3] = __float_as_uint(p.y);

            #pragma unroll
            for (int vt = 0; vt < 8; vt++) {
                int idx  = (kc * 8 + jj) * 72 + vt * 8 + g;
                int idx4 = idx + 4 * 72;
                unsigned b0h = __float_as_uint(Vh[idx]);
                unsigned b1h = __float_as_uint(Vh[idx4]);
                unsigned b0l = __float_as_uint(Vl[idx]);
                unsigned b1l = __float_as_uint(Vl[idx4]);
                mma_tf32(o[vt], ah, b0h, b1h);
                mma_tf32(o[vt], ah, b0l, b1l);
                mma_tf32(o[vt], al, b0h, b1h);
            }
        }
    }

    l0 += __shfl_xor_sync(0xffffffffu, l0, 1);
    l0 += __shfl_xor_sync(0xffffffffu, l0, 2);
    l1 += __shfl_xor_sync(0xffffffffu, l1, 1);
    l1 += __shfl_xor_sync(0xffffffffu, l1, 2);
    float inv0 = 1.0f / l0, inv1 = 1.0f / l1;

    float* ob = g_o + ((size_t)(b * NN) + n0 + mw) * ND + h * KD;
    #pragma unroll
    for (int vt = 0; vt < 8; vt++) {
        ob[(size_t)g * ND + vt * 8 + 2 * jj]           = o[vt][0] * inv0;
        ob[(size_t)g * ND + vt * 8 + 2 * jj + 1]       = o[vt][1] * inv0;
        ob[(size_t)(g + 8) * ND + vt * 8 + 2 * jj]     = o[vt][2] * inv1;
        ob[(size_t)(g + 8) * ND + vt * 8 + 2 * jj + 1] = o[vt][3] * inv1;
    }
}

// ---------------------------------------------------------------------------
// Kernel 4: output projection via split-tf32 mma.sync.
// out[b][dout][n] = sum_j wout[dout][j] * g_o[b][n][j]
// A = wout[dout][j] (row-major), B = O[n][j] (col-major n, k=j).
// CTA tile: 64(dout) x 128(n). 8 warps = 4(m) x 2(n); warp: m16 x n64.
// ---------------------------------------------------------------------------
__global__ void __launch_bounds__(256) out_mma_kernel(const float* __restrict__ wout,
                                                      float* __restrict__ out) {
    int b   = blockIdx.z;
    int do0 = blockIdx.y * 64;
    int n0  = blockIdx.x * 128;

    __shared__ float Wh[64][20],  Wl[64][20];    // [dout][j16]
    __shared__ float Oh[128][20], Ol[128][20];   // [n][j16]

    int tid = threadIdx.x;
    int warp = tid >> 5, lane = tid & 31;
    int g = lane >> 2, jj = lane & 3;
    int wm = (warp & 3) * 16;
    int wn = (warp >> 2) * 64;

    float acc[8][4] = {};

    const float* ob = g_o + (size_t)b * NN * ND;
    int wrowi = tid >> 2, wj4 = tid & 3;
    const float* wrow = wout + (size_t)(do0 + wrowi) * ND;

    for (int j0 = 0; j0 < ND; j0 += 16) {
        {   // stage W
            float4 w4 = *(const float4*)&wrow[j0 + wj4 * 4];
            float2 s0 = tf32_split(w4.x), s1 = tf32_split(w4.y);
            float2 s2 = tf32_split(w4.z), s3 = tf32_split(w4.w);
            *(float4*)&Wh[wrowi][wj4 * 4] = make_float4(s0.x, s1.x, s2.x, s3.x);
            *(float4*)&Wl[wrowi][wj4 * 4] = make_float4(s0.y, s1.y, s2.y, s3.y);
        }
        #pragma unroll
        for (int r = 0; r < 2; r++) {   // stage O
            int f4 = tid + 256 * r;
            int n = f4 >> 2, jq = f4 & 3;
            float4 o4 = *(const float4*)&ob[(size_t)(n0 + n) * ND + j0 + jq * 4];
            float2 s0 = tf32_split(o4.x), s1 = tf32_split(o4.y);
            float2 s2 = tf32_split(o4.z), s3 = tf32_split(o4.w);
            *(float4*)&Oh[n][jq * 4] = make_float4(s0.x, s1.x, s2.x, s3.x);
            *(float4*)&Ol[n][jq * 4] = make_float4(s0.y, s1.y, s2.y, s3.y);
        }
        __syncthreads();

        #pragma unroll
        for (int kc = 0; kc < 2; kc++) {
            int k0 = kc * 8;
            unsigned ah[4], al[4];
            ah[0] = __float_as_uint(Wh[wm + g][k0 + jj]);
            ah[1] = __float_as_uint(Wh[wm + g + 8][k0 + jj]);
            ah[2] = __float_as_uint(Wh[wm + g][k0 + jj + 4]);
            ah[3] = __float_as_uint(Wh[wm + g + 8][k0 + jj + 4]);
            al[0] = __float_as_uint(Wl[wm + g][k0 + jj]);
            al[1] = __float_as_uint(Wl[wm + g + 8][k0 + jj]);
            al[2] = __float_as_uint(Wl[wm + g][k0 + jj + 4]);
            al[3] = __float_as_uint(Wl[wm + g + 8][k0 + jj + 4]);
            #pragma unroll
            for (int nt = 0; nt < 8; nt++) {
                unsigned bh0 = __float_as_uint(Oh[wn + nt * 8 + g][k0 + jj]);
                unsigned bh1 = __float_as_uint(Oh[wn + nt * 8 + g][k0 + jj + 4]);
                unsigned bl0 = __float_as_uint(Ol[wn + nt * 8 + g][k0 + jj]);
                unsigned bl1 = __float_as_uint(Ol[wn + nt * 8 + g][k0 + jj + 4]);
                mma_tf32(acc[nt], ah, bh0, bh1);
                mma_tf32(acc[nt], ah, bl0, bl1);
                mma_tf32(acc[nt], al, bh0, bh1);
            }
        }
        __syncthreads();
    }

    // Epilogue: row dout = do0+wm+g (+8), col n = n0+wn+nt*8+2jj
    int d0r = do0 + wm + g;
    #pragma unroll
    for (int nt = 0; nt < 8; nt++) {
        int col = n0 + wn + nt * 8 + 2 * jj;
        *(float2*)&out[((size_t)b * ND + d0r) * NN + col] =
            make_float2(acc[nt][0], acc[nt][1]);
        *(float2*)&out[((size_t)b * ND + d0r + 8) * NN + col] =
            make_float2(acc[nt][2], acc[nt][3]);
    }
}

// ---------------------------------------------------------------------------
// Launch
// ---------------------------------------------------------------------------
extern "C" void kernel_launch(void* const* d_in, const int* in_sizes, int n_in,
                              void* d_out, int out_size) {
    const float* x  = (const float*)d_in[0];  // [8, 512, 32, 32]
    const float* wq = (const float*)d_in[1];  // [8, 64, 512]
    const float* wk = (const float*)d_in[2];  // [512, 64]
    const float* wv = (const float*)d_in[3];  // [512, 64]
    const float* wo = (const float*)d_in[4];  // [512, 8, 64]
    float* out      = (float*)d_out;          // [8, 512, 32, 32]

    pack_wkv_kernel<<<256, 256>>>(wk, wv);
    qkv_mma_kernel<<<dim3(10, 8, NB), 256>>>(x, wq);
    attn_mma_kernel<<<dim3(16, NH, NB), 128>>>();
    out_mma_kernel<<<dim3(8, 8, NB), 256>>>(wo, out);
}